// round 16
// baseline (speedup 1.0000x reference)
#include <cuda_runtime.h>
#include <cuda_bf16.h>
#include <math.h>
#include <stdint.h>

// Problem constants
#define B_SZ   8
#define L_SEQ  4096
#define D_MODEL 512
#define NC     128
#define NSTATE 64
#define NTAPS  32
#define M_ROWS (B_SZ * L_SEQ)   // 32768

// Operand images for the GEMMs (row-pair + k-interleave layout, see below).
// A-side (g_z, g_y): P-major; P = (u>>4)*8 + (u&7) pairs rows (u, u+8).
//   float4 unit idx = P*256 + s*16 + ((kappa*2+pos) ^ ((P&1)<<2))
// B-side (g_wti, g_wto): stage-major; unit idx = s*4096 + P*16 + w.
__device__ float g_z  [M_ROWS * D_MODEL];   // LN output image (A of GEMM1)
__device__ float g_z1 [M_ROWS * D_MODEL];   // in-proj output (natural layout)
__device__ float g_y  [M_ROWS * D_MODEL];   // FIR output image (A of GEMM2)
__device__ float g_k  [NC * NTAPS];
__device__ float g_wti[D_MODEL * D_MODEL];  // Win^T image  (B of GEMM1)
__device__ float g_wto[D_MODEL * D_MODEL];  // Wout^T image (B of GEMM2)

// ---------------------------------------------------------------------------
// Helpers
// ---------------------------------------------------------------------------
__device__ __forceinline__ float to_tf32(float f) {
    uint32_t u;
    asm("cvt.rna.tf32.f32 %0, %1;" : "=r"(u) : "f"(f));
    return __uint_as_float(u);
}
__device__ __forceinline__ uint32_t smem_u32(const void* p) {
    uint32_t a;
    asm("{ .reg .u64 t; cvta.to.shared.u64 t, %1; cvt.u32.u64 %0, t; }" : "=r"(a) : "l"(p));
    return a;
}
__device__ __forceinline__ void cp16(uint32_t dst, const void* src) {
    asm volatile("cp.async.cg.shared.global [%0], [%1], 16;" :: "r"(dst), "l"(src));
}
#define CP_COMMIT() asm volatile("cp.async.commit_group;" ::: "memory")
#define CP_WAIT(n)  asm volatile("cp.async.wait_group %0;" :: "n"(n) : "memory")

// m16n8k8 tf32 warp MMA
__device__ __forceinline__ void mma_tf32(float c[4],
                                         float a0, float a1, float a2, float a3,
                                         float b0, float b1)
{
    asm volatile(
        "mma.sync.aligned.m16n8k8.row.col.f32.tf32.tf32.f32 "
        "{%0,%1,%2,%3}, {%4,%5,%6,%7}, {%8,%9}, {%0,%1,%2,%3};"
        : "+f"(c[0]), "+f"(c[1]), "+f"(c[2]), "+f"(c[3])
        : "r"(__float_as_uint(a0)), "r"(__float_as_uint(a1)),
          "r"(__float_as_uint(a2)), "r"(__float_as_uint(a3)),
          "r"(__float_as_uint(b0)), "r"(__float_as_uint(b1)));
}

// f32x2 packed math
__device__ __forceinline__ uint64_t pk2(float a, float b) {
    uint64_t r; asm("mov.b64 %0, {%1, %2};" : "=l"(r) : "f"(a), "f"(b)); return r;
}
__device__ __forceinline__ void upk2(uint64_t v, float& a, float& b) {
    asm("mov.b64 {%0, %1}, %2;" : "=f"(a), "=f"(b) : "l"(v));
}
__device__ __forceinline__ uint64_t addx2(uint64_t a, uint64_t b) {
    uint64_t r; asm("add.rn.f32x2 %0, %1, %2;" : "=l"(r) : "l"(a), "l"(b)); return r;
}
__device__ __forceinline__ uint64_t mulx2(uint64_t a, uint64_t b) {
    uint64_t r; asm("mul.rn.f32x2 %0, %1, %2;" : "=l"(r) : "l"(a), "l"(b)); return r;
}
__device__ __forceinline__ uint64_t fmax2(uint64_t a, uint64_t b, uint64_t c) {
    uint64_t r; asm("fma.rn.f32x2 %0, %1, %2, %3;" : "=l"(r) : "l"(a), "l"(b), "l"(c)); return r;
}

// ---------------------------------------------------------------------------
// Combined prep kernel:
//   [0, 16384)        LayerNorm, pair rows (u, u+8) per block -> g_z image
//   [16384, 16896)    B-image gather for Win^T / Wout^T (tf32-rounded)
//   [16896, 16912)    FIR taps
// ---------------------------------------------------------------------------
#define PREP_LN    16384
#define PREP_WT    (PREP_LN + 512)
#define PREP_TOTAL (PREP_WT + 16)

__global__ __launch_bounds__(256)
void prep_kernel(const float* __restrict__ x,
                 const float* __restrict__ gam, const float* __restrict__ bet,
                 const float* __restrict__ Win, const float* __restrict__ Wout,
                 const float* __restrict__ lre, const float* __restrict__ lim,
                 const float* __restrict__ Bm,  const float* __restrict__ cre,
                 const float* __restrict__ cim)
{
    int bid = blockIdx.x;
    int tid = threadIdx.x;

    if (bid < PREP_LN) {
        // pid = row-pair id: rows u = (pid>>3)*16 + (pid&7) and u+8
        int pid  = bid;
        int half = tid >> 7;
        int t    = tid & 127;
        int row  = (pid >> 3) * 16 + (pid & 7) + half * 8;
        float4 v = ((const float4*)(x + (size_t)row * D_MODEL))[t];
        float s  = v.x + v.y + v.z + v.w;
        float sq = v.x*v.x + v.y*v.y + v.z*v.z + v.w*v.w;
        #pragma unroll
        for (int off = 16; off > 0; off >>= 1) {
            s  += __shfl_xor_sync(0xFFFFFFFFu, s,  off);
            sq += __shfl_xor_sync(0xFFFFFFFFu, sq, off);
        }
        __shared__ float ss[8], ssq[8];
        __shared__ float4 sEx[256];
        int warp = tid >> 5, lane = tid & 31;
        if (lane == 0) { ss[warp] = s; ssq[warp] = sq; }
        __syncthreads();
        int w0 = half * 4;
        float tots = ss[w0] + ss[w0+1] + ss[w0+2] + ss[w0+3];
        float totq = ssq[w0] + ssq[w0+1] + ssq[w0+2] + ssq[w0+3];
        float mu  = tots * (1.0f / D_MODEL);
        float var = totq * (1.0f / D_MODEL) - mu * mu;
        float inv = rsqrtf(var + 1e-5f);
        float4 gg = ((const float4*)gam)[t];
        float4 bb = ((const float4*)bet)[t];
        float4 o;
        o.x = to_tf32((v.x - mu) * inv * gg.x + bb.x);
        o.y = to_tf32((v.y - mu) * inv * gg.y + bb.y);
        o.z = to_tf32((v.z - mu) * inv * gg.z + bb.z);
        o.w = to_tf32((v.w - mu) * inv * gg.w + bb.w);
        // k-interleave within 8-groups via lane-pair shuffles (same as before)
        float rx = __shfl_xor_sync(0xFFFFFFFFu, o.x, 1);
        float ry = __shfl_xor_sync(0xFFFFFFFFu, o.y, 1);
        float rz = __shfl_xor_sync(0xFFFFFFFFu, o.z, 1);
        float rw = __shfl_xor_sync(0xFFFFFFFFu, o.w, 1);
        float4 st = ((t & 1) == 0) ? make_float4(o.x, rx, o.y, ry)
                                   : make_float4(rz, o.z, rw, o.w);
        sEx[tid] = st;
        __syncthreads();
        // assemble 16B row-pair units: tid = sKI*16 + kap*2 + pos
        int sKI = tid >> 4, kap = (tid >> 1) & 7, pos = tid & 1;
        float4 lo = sEx[sKI * 8 + kap];
        float4 hi = sEx[sKI * 8 + kap + 128];
        float4 un = pos ? make_float4(lo.z, lo.w, hi.z, hi.w)
                        : make_float4(lo.x, lo.y, hi.x, hi.y);
        size_t idx = (size_t)pid * 256 + (size_t)(tid ^ ((pid & 1) << 2));
        ((float4*)g_z)[idx] = un;
    } else if (bid < PREP_WT) {
        // B-image gather: 256 blocks per matrix, one 16B unit per thread
        int ti = bid - PREP_LN;
        const float* W;
        float* Bi;
        if (ti < 256) { W = Win;  Bi = g_wti; }
        else          { W = Wout; Bi = g_wto; ti -= 256; }
        int unit = ti * 256 + tid;          // 0..65535
        int s    = unit >> 12;              // stage 0..15
        int rem  = unit & 4095;
        int P    = rem >> 4;                // n-pair 0..255
        int w    = rem & 15;
        int v    = w ^ ((P & 1) << 2);
        int kap  = v >> 1, pos = v & 1;
        int n    = (P >> 3) * 16 + (P & 7);
        int j    = 8 * (kap >> 1) + (kap & 1) * 2 + pos;
        int k    = 32 * s + j;
        float4 u4;
        u4.x = to_tf32(W[(size_t)k * D_MODEL + n]);
        u4.y = to_tf32(W[(size_t)(k + 4) * D_MODEL + n]);
        u4.z = to_tf32(W[(size_t)k * D_MODEL + n + 8]);
        u4.w = to_tf32(W[(size_t)(k + 4) * D_MODEL + n + 8]);
        ((float4*)Bi)[unit] = u4;
    } else {
        int c = (bid - PREP_WT) * 8 + (tid >> 5);
        int tau = tid & 31;
        float ft = (float)tau;
        float acc = 0.0f;
        #pragma unroll 8
        for (int n = 0; n < NSTATE; n++) {
            int idx = c * NSTATE + n;
            float re = lre[idx], im = lim[idx], bn = Bm[idx];
            float cr = cre[idx] * bn, ci = cim[idx] * bn;
            float s, co;
            sincosf(im * ft, &s, &co);
            acc += expf(re * ft) * (cr * co - ci * s);
        }
        g_k[c * NTAPS + tau] = acc;
    }
}

// ---------------------------------------------------------------------------
// Warp-MMA tf32 GEMM. CTA tile 128x128, BK=32, 8 warps (2m x 4n), m16n8k8,
// 2 CTAs/SM. Row-pair operand images -> LDS.128 fragments (4 A + 2 B per ks,
// was 12 LDS.64). Linear image staging (smem off = tid*16 + 4096*i).
// 3-stage cp.async pipeline, literal buffer indices, single barrier/stage.
// ---------------------------------------------------------------------------
__device__ __forceinline__ float gelu_exact(float v) {
    return 0.5f * v * (1.0f + erff(v * 0.70710678118654752f));
}

#define STG_A 16384
#define STG_BYTES 32768                  // A(16KB) + B(16KB) per stage
#define NSTAGE 3
#define GEMM_SMEM (NSTAGE * STG_BYTES)   // 96KB

template<int EPI>
__global__ __launch_bounds__(256, 2)
void gemm_mma(const float* __restrict__ A, const float* __restrict__ Bt,
              const float* __restrict__ bias, const float* __restrict__ resid,
              float* __restrict__ C)
{
    extern __shared__ __align__(16) char sm[];
    uint32_t ubase = smem_u32(sm);

    int tid = threadIdx.x;
    int lane = tid & 31;
    int wid  = tid >> 5;
    int wm = wid >> 2;       // 0..1
    int wn = wid & 3;        // 0..3
    int g  = lane >> 2;      // 0..7
    int t4 = lane & 3;       // 0..3

    // fragment addressing: unit(Ploc, kap, pos) at Ploc*256 + ((kap*32+pos*16)^((Ploc&1)<<6))
    // Ploc&1 == g&1 for all fragments.
    uint32_t go[4];
    #pragma unroll
    for (int ks = 0; ks < 4; ks++)
        go[ks] = (uint32_t)((((2 * ks + (t4 >> 1)) * 32 + (t4 & 1) * 16)) ^ ((g & 1) << 6));
    uint32_t aoff[4], boff[2];
    #pragma unroll
    for (int mt = 0; mt < 4; mt++) aoff[mt] = (uint32_t)(((wm * 4 + mt) * 8 + g) * 256);
    #pragma unroll
    for (int q = 0; q < 2; q++) boff[q] = (uint32_t)(STG_A + ((wn * 2 + q) * 8 + g) * 256);

    int bn = blockIdx.x, bm = blockIdx.y;
    int rowA = bm * 128;

    // staging: linear image copies
    uint32_t so0 = ubase + (uint32_t)(tid * 16);
    const float* aP = A  + ((size_t)(bm * 64 + (tid >> 4))) * 1024 + (tid & 15) * 4;
    const float* bP = Bt + (size_t)bn * 4096 + (size_t)tid * 4;

    float acc[4][4][4];
    #pragma unroll
    for (int mt = 0; mt < 4; mt++)
        #pragma unroll
        for (int nt = 0; nt < 4; nt++)
            #pragma unroll
            for (int q = 0; q < 4; q++) acc[mt][nt][q] = 0.0f;

    // prefetch one stage into buffer at byte offset BB; advances aP/bP
    auto gprefetch = [&](uint32_t BB) {
        cp16(so0 + BB,          aP);
        cp16(so0 + BB +  4096,  aP + 16384);
        cp16(so0 + BB +  8192,  aP + 32768);
        cp16(so0 + BB + 12288,  aP + 49152);
        cp16(so0 + BB + STG_A,          bP);
        cp16(so0 + BB + STG_A +  4096,  bP + 1024);
        cp16(so0 + BB + STG_A +  8192,  bP + 2048);
        cp16(so0 + BB + STG_A + 12288,  bP + 3072);
        aP += 64; bP += 16384;
        CP_COMMIT();
    };

    auto gcompute = [&](const char* cbuf) {
        #pragma unroll
        for (int ks = 0; ks < 4; ks++) {
            float4 aq[4], bq[2];
            #pragma unroll
            for (int mt = 0; mt < 4; mt++)
                aq[mt] = *(const float4*)(cbuf + aoff[mt] + go[ks]);
            #pragma unroll
            for (int q = 0; q < 2; q++)
                bq[q] = *(const float4*)(cbuf + boff[q] + go[ks]);
            #pragma unroll
            for (int mt = 0; mt < 4; mt++)
                #pragma unroll
                for (int q = 0; q < 2; q++) {
                    mma_tf32(acc[mt][2*q],     aq[mt].x, aq[mt].z, aq[mt].y, aq[mt].w,
                             bq[q].x, bq[q].y);
                    mma_tf32(acc[mt][2*q + 1], aq[mt].x, aq[mt].z, aq[mt].y, aq[mt].w,
                             bq[q].z, bq[q].w);
                }
        }
    };

    // prologue: stage 0 -> buf0, stage 1 -> buf1
    gprefetch(0);
    gprefetch(STG_BYTES);

    #pragma unroll 1
    for (int it = 0; it < 4; it++) {
        CP_WAIT(1); __syncthreads(); gprefetch(2 * STG_BYTES); gcompute(sm);
        CP_WAIT(1); __syncthreads(); gprefetch(0);             gcompute(sm + STG_BYTES);
        CP_WAIT(1); __syncthreads(); gprefetch(STG_BYTES);     gcompute(sm + 2 * STG_BYTES);
    }
    CP_WAIT(1); __syncthreads(); gprefetch(2 * STG_BYTES); gcompute(sm);
    CP_WAIT(1); __syncthreads(); gprefetch(0);             gcompute(sm + STG_BYTES);
    CP_WAIT(1); __syncthreads();                           gcompute(sm + 2 * STG_BYTES);
    CP_WAIT(0); __syncthreads();                           gcompute(sm);

    // epilogue (natural-layout C, unchanged)
    #pragma unroll
    for (int mt = 0; mt < 4; mt++) {
        size_t r0 = (size_t)rowA + wm * 64 + mt * 16 + g;
        size_t r1 = r0 + 8;
        #pragma unroll
        for (int nt = 0; nt < 4; nt++) {
            int col = bn * 128 + wn * 32 + nt * 8 + 2 * t4;
            float b0 = bias[col], b1 = bias[col + 1];
            float v0 = acc[mt][nt][0] + b0;
            float v1 = acc[mt][nt][1] + b1;
            float v2 = acc[mt][nt][2] + b0;
            float v3 = acc[mt][nt][3] + b1;
            if (EPI == 1) {
                const float* rr0 = resid + r0 * D_MODEL + col;
                const float* rr1 = resid + r1 * D_MODEL + col;
                v0 = rr0[0] + gelu_exact(v0);
                v1 = rr0[1] + gelu_exact(v1);
                v2 = rr1[0] + gelu_exact(v2);
                v3 = rr1[1] + gelu_exact(v3);
            }
            *(float2*)(C + r0 * D_MODEL + col) = make_float2(v0, v1);
            *(float2*)(C + r1 * D_MODEL + col) = make_float2(v2, v3);
        }
    }
}

// ---------------------------------------------------------------------------
// Bidirectional 32-tap FIR + D skip. Block = 8 chunks x 256 rows, 256 threads.
// Circular register windows (R15). Store path: xor-1 shuffle assembles the
// k-interleaved 16B, then xor-8 shuffle pairs rows (u, u+8) -> one STG.128
// per row into the g_y A-image.
// ---------------------------------------------------------------------------
#define FT_BLK 256
#define FIR_ROWS (FT_BLK + 2 * NTAPS + 1)   // 321

__global__ __launch_bounds__(256)
void fir_kernel(const float* __restrict__ Dvec)
{
    int c0 = blockIdx.y * 8;
    int b  = blockIdx.z;
    int t0 = blockIdx.x * FT_BLK;
    int tid = threadIdx.x;

    __shared__ float4 su[FIR_ROWS][8];   // [local row][chunk]
    __shared__ float  sk[8][33];         // padded taps

    const float4* u4 = (const float4*)g_z1;
    for (int slot = tid; slot < FIR_ROWS * 8; slot += 256) {
        int row = slot >> 3, cc = slot & 7;
        int t = t0 - 32 + row;
        float4 v = make_float4(0.f, 0.f, 0.f, 0.f);
        if (t >= 0 && t < L_SEQ) v = u4[((size_t)b * L_SEQ + t) * NC + c0 + cc];
        su[row][cc] = v;
    }
    {
        int cc = tid >> 5, tau = tid & 31;
        sk[cc][tau] = g_k[(c0 + cc) * NTAPS + tau];
    }
    __syncthreads();

    int c  = tid & 7;          // chunk within group (= kappa)
    int rg = tid >> 3;         // row group 0..31
    int w  = rg * 8;           // first output row (local)

    ulonglong2 F[8], Bw[8];
    #pragma unroll
    for (int i = 0; i < 8; i++) {
        F[i]             = *(const ulonglong2*)&su[w + 32 + i][c];
        Bw[(33 + i) & 7] = *(const ulonglong2*)&su[w + 33 + i][c];
    }

    float dv = Dvec[c0 + c];
    uint64_t dv2 = pk2(dv, dv);
    uint64_t aL[8], aH[8];
    #pragma unroll
    for (int r = 0; r < 8; r++) {
        aL[r] = mulx2(dv2, F[r].x);
        aH[r] = mulx2(dv2, F[r].y);
    }

    #pragma unroll
    for (int tau = 0; tau < NTAPS; tau++) {
        float kt = sk[c][tau];
        uint64_t k2 = pk2(kt, kt);
        #pragma unroll
        for (int r = 0; r < 8; r++) {
            ulonglong2 fs = F[(32 + r - tau) & 7];
            ulonglong2 bs = Bw[(33 + r + tau) & 7];
            aL[r] = fmax2(k2, addx2(fs.x, bs.x), aL[r]);
            aH[r] = fmax2(k2, addx2(fs.y, bs.y), aH[r]);
        }
        if (tau < NTAPS - 1) {
            F[(31 - tau) & 7]  = *(const ulonglong2*)&su[w + 31 - tau][c];
            Bw[(41 + tau) & 7] = *(const ulonglong2*)&su[w + 41 + tau][c];
        }
    }

    // store into g_y A-image
    int s_out = blockIdx.y;                   // stage index = (c0+c)>>3
    int pos   = rg & 1;
    size_t Phi = ((((size_t)b * L_SEQ + t0) >> 4) + (size_t)(rg >> 1)) * 8;
    float4* yimg = (float4*)g_y;
    #pragma unroll
    for (int r = 0; r < 8; r++) {
        float4 o;
        upk2(aL[r], o.x, o.y);
        upk2(aH[r], o.z, o.w);
        o.x = to_tf32(o.x); o.y = to_tf32(o.y); o.z = to_tf32(o.z); o.w = to_tf32(o.w);
        // xor-1: assemble k-interleaved 16B for this row/chunk-pair
        float rx = __shfl_xor_sync(0xFFFFFFFFu, o.x, 1);
        float ry = __shfl_xor_sync(0xFFFFFFFFu, o.y, 1);
        float rz = __shfl_xor_sync(0xFFFFFFFFu, o.z, 1);
        float rw = __shfl_xor_sync(0xFFFFFFFFu, o.w, 1);
        float4 st = ((c & 1) == 0) ? make_float4(o.x, rx, o.y, ry)
                                   : make_float4(rz, o.z, rw, o.w);
        // xor-8: pair rows (u, u+8)
        float px = __shfl_xor_sync(0xFFFFFFFFu, st.x, 8);
        float py = __shfl_xor_sync(0xFFFFFFFFu, st.y, 8);
        float pz = __shfl_xor_sync(0xFFFFFFFFu, st.z, 8);
        float pw = __shfl_xor_sync(0xFFFFFFFFu, st.w, 8);
        float4 un = (pos == 0) ? make_float4(st.x, st.y, px, py)
                               : make_float4(pz, pw, st.z, st.w);
        size_t P = Phi + (size_t)r;
        size_t idx = P * 256 + s_out * 16 + (size_t)((c * 2 + pos) ^ ((r & 1) << 2));
        yimg[idx] = un;
    }
}

// ---------------------------------------------------------------------------
// Launch
// ---------------------------------------------------------------------------
extern "C" void kernel_launch(void* const* d_in, const int* in_sizes, int n_in,
                              void* d_out, int out_size)
{
    const float* x    = (const float*)d_in[0];
    const float* ln_g = (const float*)d_in[1];
    const float* ln_b = (const float*)d_in[2];
    const float* Win  = (const float*)d_in[3];
    const float* bin_ = (const float*)d_in[4];
    const float* Wout = (const float*)d_in[5];
    const float* bout = (const float*)d_in[6];
    const float* lre  = (const float*)d_in[7];
    const float* lim  = (const float*)d_in[8];
    const float* Bm   = (const float*)d_in[9];
    const float* cre  = (const float*)d_in[10];
    const float* cim  = (const float*)d_in[11];
    const float* Dvec = (const float*)d_in[12];
    float* out = (float*)d_out;

    float *z, *z1, *y, *wti, *wto;
    cudaGetSymbolAddress((void**)&z,   g_z);
    cudaGetSymbolAddress((void**)&z1,  g_z1);
    cudaGetSymbolAddress((void**)&y,   g_y);
    cudaGetSymbolAddress((void**)&wti, g_wti);
    cudaGetSymbolAddress((void**)&wto, g_wto);

    cudaFuncSetAttribute(gemm_mma<0>, cudaFuncAttributeMaxDynamicSharedMemorySize, GEMM_SMEM);
    cudaFuncSetAttribute(gemm_mma<1>, cudaFuncAttributeMaxDynamicSharedMemorySize, GEMM_SMEM);

    // 1. combined prep: LayerNorm image + B images + FIR taps
    prep_kernel<<<PREP_TOTAL, 256>>>(x, ln_g, ln_b, Win, Wout, lre, lim, Bm, cre, cim);

    // 2. in-projection: z1 = z @ Win + bin
    gemm_mma<0><<<dim3(4, 256), 256, GEMM_SMEM>>>(z, wti, bin_, nullptr, z1);

    // 3. bidirectional FIR + D skip
    fir_kernel<<<dim3(L_SEQ / FT_BLK, NC / 8, B_SZ), 256>>>(Dvec);

    // 4. out-projection + gelu + residual -> d_out
    gemm_mma<1><<<dim3(4, 256), 256, GEMM_SMEM>>>(y, wto, bout, x, out);
}